// round 1
// baseline (speedup 1.0000x reference)
#include <cuda_runtime.h>
#include <cuda_bf16.h>
#include <cstddef>

// ---------------------------------------------------------------------------
// Blended-expert MLP: per layer  y[b,o] = sum_e blend[b,e] * (W_e @ h_b)[o]
//                                        + sum_e blend[b,e] * Bias_e[o]
// Folded into ONE dense GEMM per layer:
//   A[b, e*K_IN + i] = blend[b,e] * h[b,i]   (built on the fly at tile load)
//   B[e*K_IN + i, n] = W[e, n, i]            (contiguous along i -> coalesced)
// Inner loop uses Blackwell packed fma.rn.f32x2 (2 fp32 FMA / instruction).
// ---------------------------------------------------------------------------

#define BM 128
#define BN 128
#define BK 16
#define NTHREADS 256
#define SSTRIDE 132   // padded smem row stride (floats); 132*4=528 is 16B-aligned

// ping-pong activation buffers (static device memory; no allocations)
__device__ float g_h1[4096 * 1024];
__device__ float g_h2[4096 * 1024];

__device__ __forceinline__ void fma2(unsigned long long& d,
                                     unsigned long long a,
                                     unsigned long long b) {
    asm("fma.rn.f32x2 %0, %1, %2, %0;" : "+l"(d) : "l"(a), "l"(b));
}

__device__ __forceinline__ unsigned long long pack2(float x) {
    unsigned long long r;
    unsigned int xi = __float_as_uint(x);
    asm("mov.b64 %0, {%1, %1};" : "=l"(r) : "r"(xi));
    return r;
}

__device__ __forceinline__ float2 unpack2(unsigned long long v) {
    unsigned int lo, hi;
    asm("mov.b64 {%0, %1}, %2;" : "=r"(lo), "=r"(hi) : "l"(v));
    return make_float2(__uint_as_float(lo), __uint_as_float(hi));
}

template <int K_IN, bool DO_ELU>
__global__ __launch_bounds__(NTHREADS, 2)
void blended_gemm(const float* __restrict__ h,      // (4096, K_IN)
                  const float* __restrict__ blend,  // (4096, 8)
                  const float* __restrict__ W,      // (8, N, K_IN)
                  const float* __restrict__ Bias,   // (8, N)
                  float* __restrict__ out,          // (4096, N)
                  int N) {
    constexpr int E = 8;
    constexpr int K = E * K_IN;
    constexpr int KSHIFT = (K_IN == 512) ? 9 : 10;
    constexpr int KMASK = K_IN - 1;

    __shared__ float As[BK * SSTRIDE];
    __shared__ float Bs[BK * SSTRIDE];

    const int tid  = threadIdx.x;
    const int trow = tid >> 4;   // 0..15
    const int tcol = tid & 15;   // 0..15
    const int mBase = blockIdx.y * BM;
    const int nBase = blockIdx.x * BN;

    // tile-load mapping: 512 float4 slots, 2 per thread
    const int lrow0 = tid >> 2;          // 0..63
    const int lkq   = (tid & 3) * 4;     // k offset {0,4,8,12}

    unsigned long long acc[8][4];
#pragma unroll
    for (int i = 0; i < 8; i++)
#pragma unroll
        for (int j = 0; j < 4; j++) acc[i][j] = 0ULL;

    for (int kT = 0; kT < K; kT += BK) {
        // ---- A tile: blend-scaled activations, stored transposed As[k][m] ----
#pragma unroll
        for (int s = 0; s < 2; s++) {
            int row = lrow0 + s * 64;
            int kg  = kT + lkq;
            int e   = kg >> KSHIFT;
            int i   = kg & KMASK;
            float4 v = *(const float4*)(h + (size_t)(mBase + row) * K_IN + i);
            float bl = blend[(mBase + row) * E + e];
            v.x *= bl; v.y *= bl; v.z *= bl; v.w *= bl;
            As[(lkq + 0) * SSTRIDE + row] = v.x;
            As[(lkq + 1) * SSTRIDE + row] = v.y;
            As[(lkq + 2) * SSTRIDE + row] = v.z;
            As[(lkq + 3) * SSTRIDE + row] = v.w;
        }
        // ---- B tile: W[e,n,i] contiguous along i(=k), stored Bs[k][n] ----
#pragma unroll
        for (int s = 0; s < 2; s++) {
            int n  = lrow0 + s * 64;
            int kg = kT + lkq;
            int e  = kg >> KSHIFT;
            int i  = kg & KMASK;
            float4 v = *(const float4*)(W + ((size_t)e * N + nBase + n) * K_IN + i);
            Bs[(lkq + 0) * SSTRIDE + n] = v.x;
            Bs[(lkq + 1) * SSTRIDE + n] = v.y;
            Bs[(lkq + 2) * SSTRIDE + n] = v.z;
            Bs[(lkq + 3) * SSTRIDE + n] = v.w;
        }
        __syncthreads();

#pragma unroll
        for (int kk = 0; kk < BK; kk++) {
            const float4 a0 = *(const float4*)&As[kk * SSTRIDE + trow * 4];
            const float4 a1 = *(const float4*)&As[kk * SSTRIDE + 64 + trow * 4];
            const ulonglong2 b0 = *(const ulonglong2*)&Bs[kk * SSTRIDE + tcol * 4];
            const ulonglong2 b1 = *(const ulonglong2*)&Bs[kk * SSTRIDE + 64 + tcol * 4];

            unsigned long long aa[8];
            aa[0] = pack2(a0.x); aa[1] = pack2(a0.y);
            aa[2] = pack2(a0.z); aa[3] = pack2(a0.w);
            aa[4] = pack2(a1.x); aa[5] = pack2(a1.y);
            aa[6] = pack2(a1.z); aa[7] = pack2(a1.w);
#pragma unroll
            for (int r = 0; r < 8; r++) {
                fma2(acc[r][0], aa[r], b0.x);
                fma2(acc[r][1], aa[r], b0.y);
                fma2(acc[r][2], aa[r], b1.x);
                fma2(acc[r][3], aa[r], b1.y);
            }
        }
        __syncthreads();
    }

    // ---- epilogue: blended bias + optional ELU ----
    // stage this tile's bias columns in shared (reuse As)
    float* biasS = As;
    for (int idx = tid; idx < E * BN; idx += NTHREADS) {
        int e = idx >> 7;
        int n = idx & 127;
        biasS[idx] = Bias[e * N + nBase + n];
    }
    __syncthreads();

#pragma unroll
    for (int rb = 0; rb < 2; rb++) {
#pragma unroll
        for (int rr = 0; rr < 4; rr++) {
            const int r  = rb * 4 + rr;
            const int rg = mBase + rb * 64 + trow * 4 + rr;
            const float4 bl0 = *(const float4*)(blend + (size_t)rg * E);
            const float4 bl1 = *(const float4*)(blend + (size_t)rg * E + 4);
            const float blv[8] = {bl0.x, bl0.y, bl0.z, bl0.w,
                                  bl1.x, bl1.y, bl1.z, bl1.w};
#pragma unroll
            for (int cb = 0; cb < 2; cb++) {
                float4 res;
                float* rp = &res.x;
#pragma unroll
                for (int cc = 0; cc < 4; cc++) {
                    const int cl = cb * 64 + tcol * 4 + cc;  // col within tile
                    float2 p = unpack2(acc[r][cb * 2 + (cc >> 1)]);
                    float v = (cc & 1) ? p.y : p.x;
                    float bias = 0.f;
#pragma unroll
                    for (int e = 0; e < 8; e++) bias += blv[e] * biasS[e * BN + cl];
                    v += bias;
                    if (DO_ELU) v = (v > 0.f) ? v : expm1f(v);
                    rp[cc] = v;
                }
                *(float4*)(out + (size_t)rg * N + nBase + cb * 64 + tcol * 4) = res;
            }
        }
    }
}

extern "C" void kernel_launch(void* const* d_in, const int* in_sizes, int n_in,
                              void* d_out, int out_size) {
    const float* blend = (const float*)d_in[0];  // (4096, 8)
    const float* x     = (const float*)d_in[1];  // (4096, 512)
    const float* W0    = (const float*)d_in[2];  // (8, 1024, 512)
    const float* B0    = (const float*)d_in[3];  // (8, 1024)
    const float* W1    = (const float*)d_in[4];  // (8, 1024, 1024)
    const float* B1    = (const float*)d_in[5];  // (8, 1024)
    const float* W2    = (const float*)d_in[6];  // (8, 512, 1024)
    const float* B2    = (const float*)d_in[7];  // (8, 512)
    float* out = (float*)d_out;                  // (4096, 512)

    float* h1 = nullptr;
    float* h2 = nullptr;
    cudaGetSymbolAddress((void**)&h1, g_h1);
    cudaGetSymbolAddress((void**)&h2, g_h2);

    dim3 block(NTHREADS);
    // layer 0: (4096,512) -> (4096,1024), ELU
    blended_gemm<512, true><<<dim3(1024 / BN, 4096 / BM), block>>>(
        x, blend, W0, B0, h1, 1024);
    // layer 1: (4096,1024) -> (4096,1024), ELU
    blended_gemm<1024, true><<<dim3(1024 / BN, 4096 / BM), block>>>(
        h1, blend, W1, B1, h2, 1024);
    // layer 2: (4096,1024) -> (4096,512), linear
    blended_gemm<1024, false><<<dim3(512 / BN, 4096 / BM), block>>>(
        h2, blend, W2, B2, out, 512);
}

// round 3
// speedup vs baseline: 2.6119x; 2.6119x over previous
#include <cuda_runtime.h>
#include <cuda_bf16.h>
#include <cstdint>
#include <cstddef>

// ---------------- static device buffers (no runtime allocation) ----------------
__device__ __align__(256) __nv_bfloat16 g_Ahi[4096 * 8192];
__device__ __align__(256) __nv_bfloat16 g_Alo[4096 * 8192];
__device__ __align__(256) __nv_bfloat16 g_Whi[16 * 1024 * 1024];
__device__ __align__(256) __nv_bfloat16 g_Wlo[16 * 1024 * 1024];
__device__ __align__(256) float g_h[4096 * 1024];

// ---------------- helpers ----------------
__device__ __forceinline__ uint32_t smem_u32(const void* p) {
    uint32_t a;
    asm("{ .reg .u64 t; cvta.to.shared.u64 t, %1; cvt.u32.u64 %0, t; }" : "=r"(a) : "l"(p));
    return a;
}

#define CP_ASYNC16(s, g) asm volatile("cp.async.cg.shared.global [%0], [%1], 16;" ::"r"(s), "l"(g))
#define CP_COMMIT() asm volatile("cp.async.commit_group;" ::: "memory")
#define CP_WAIT1() asm volatile("cp.async.wait_group 1;" ::: "memory")

__device__ __forceinline__ void ldsm4(uint32_t& r0, uint32_t& r1, uint32_t& r2, uint32_t& r3,
                                      uint32_t addr) {
    asm volatile("ldmatrix.sync.aligned.m8n8.x4.shared.b16 {%0,%1,%2,%3}, [%4];"
                 : "=r"(r0), "=r"(r1), "=r"(r2), "=r"(r3) : "r"(addr));
}

__device__ __forceinline__ void mma16816(float* c, const uint32_t* a, const uint32_t* b) {
    asm volatile(
        "mma.sync.aligned.m16n8k16.row.col.f32.bf16.bf16.f32 "
        "{%0,%1,%2,%3}, {%4,%5,%6,%7}, {%8,%9}, {%0,%1,%2,%3};"
        : "+f"(c[0]), "+f"(c[1]), "+f"(c[2]), "+f"(c[3])
        : "r"(a[0]), "r"(a[1]), "r"(a[2]), "r"(a[3]), "r"(b[0]), "r"(b[1]));
}

// fp32 -> bf16 hi/lo split, packed pairs (low 16 bits = first element)
__device__ __forceinline__ void split2(float a, float b, uint32_t& hi, uint32_t& lo) {
    __nv_bfloat16 ha = __float2bfloat16_rn(a), hb = __float2bfloat16_rn(b);
    float ra = a - __bfloat162float(ha);
    float rb = b - __bfloat162float(hb);
    __nv_bfloat16 la = __float2bfloat16_rn(ra), lb = __float2bfloat16_rn(rb);
    hi = (uint32_t)__bfloat16_as_ushort(ha) | ((uint32_t)__bfloat16_as_ushort(hb) << 16);
    lo = (uint32_t)__bfloat16_as_ushort(la) | ((uint32_t)__bfloat16_as_ushort(lb) << 16);
}

// ---------------- weight split kernel ----------------
__global__ void wsplit(const float4* __restrict__ src, uint2* __restrict__ hi,
                       uint2* __restrict__ lo, int n4) {
    for (int i = blockIdx.x * blockDim.x + threadIdx.x; i < n4; i += gridDim.x * blockDim.x) {
        float4 v = src[i];
        uint32_t hx, lx, hz, lz;
        split2(v.x, v.y, hx, lx);
        split2(v.z, v.w, hz, lz);
        hi[i] = make_uint2(hx, hz);
        lo[i] = make_uint2(lx, lz);
    }
}

// ---------------- activation fold+split: A[b, e*K_IN+i] = blend[b,e]*h[b,i] ----------------
template <int K_IN>
__global__ void prep(const float* __restrict__ h, const float* __restrict__ blend,
                     __nv_bfloat16* __restrict__ Ahi, __nv_bfloat16* __restrict__ Alo) {
    constexpr int Q = K_IN / 4;
    int idx = blockIdx.x * blockDim.x + threadIdx.x;
    if (idx >= 4096 * Q) return;
    int b = idx / Q, q = idx - b * Q;
    float4 v = ((const float4*)h)[idx];
    float4 w0 = *(const float4*)(blend + (size_t)b * 8);
    float4 w1 = *(const float4*)(blend + (size_t)b * 8 + 4);
    float wv[8] = {w0.x, w0.y, w0.z, w0.w, w1.x, w1.y, w1.z, w1.w};
    size_t base = (size_t)b * (8 * K_IN) + q * 4;
#pragma unroll
    for (int e = 0; e < 8; e++) {
        float s = wv[e];
        uint32_t hx, lx, hz, lz;
        split2(v.x * s, v.y * s, hx, lx);
        split2(v.z * s, v.w * s, hz, lz);
        *(uint2*)(Ahi + base + e * K_IN) = make_uint2(hx, hz);
        *(uint2*)(Alo + base + e * K_IN) = make_uint2(lx, lz);
    }
}

// ---------------- GEMM: C(4096,N) = A(4096,8*K_IN) x W^T, 3-product bf16 split ----------------
// CTA tile 128(M) x NT(N) x 32(K); 8 warps, warp tile 64 x (NT/4).
template <int K_IN, int N, int NT, bool DO_ELU>
__global__ __launch_bounds__(256, 1) void gemm_mma(
    const __nv_bfloat16* __restrict__ Ahi, const __nv_bfloat16* __restrict__ Alo,
    const __nv_bfloat16* __restrict__ Wh, const __nv_bfloat16* __restrict__ Wl,
    const float* __restrict__ blend, const float* __restrict__ Bias,
    float* __restrict__ out) {
    constexpr int K = 8 * K_IN;
    constexpr int NC = K / 32;
    constexpr int AB = 128 * 64;   // bytes per A version tile
    constexpr int BB = NT * 64;    // bytes per B version tile
    constexpr int STG = 2 * AB + 2 * BB;
    constexpr int WNC = NT / 4;    // warp N extent
    constexpr int NP = WNC / 16;   // ldmatrix.x4 n-pairs per warp
    constexpr int NTT = 2 * NP;    // n8 tiles per warp

    extern __shared__ __align__(1024) char smem[];
    const uint32_t sb = smem_u32(smem);
    const int tid = threadIdx.x, wid = tid >> 5, lid = tid & 31;
    const int wm = wid & 1, wn = wid >> 1;
    const int mBase = blockIdx.y * 128, nBase = blockIdx.x * NT;

    float acc[4][NTT][4];
#pragma unroll
    for (int a = 0; a < 4; a++)
#pragma unroll
        for (int b = 0; b < NTT; b++)
#pragma unroll
            for (int c = 0; c < 4; c++) acc[a][b][c] = 0.f;

    auto swz = [](int row, int seg) -> uint32_t {
        return (uint32_t)(row * 64 + ((seg ^ ((row >> 1) & 3)) << 4));
    };

    auto cp_stage = [&](int s, int c) {
        const uint32_t st = sb + s * STG;
        const int kT = c * 32;
        // A tiles (hi+lo): 1024 x 16B
#pragma unroll
        for (int j = 0; j < 4; j++) {
            int idx = tid + 256 * j;
            int ver = idx >> 9, r = (idx >> 2) & 127, seg = idx & 3;
            const __nv_bfloat16* src =
                (ver ? Alo : Ahi) + (size_t)(mBase + r) * K + kT + seg * 8;
            CP_ASYNC16(st + ver * AB + swz(r, seg), src);
        }
        // B tiles (hi+lo): weights in (E, N, K_IN) layout
        const int e = kT / K_IN, i0 = kT % K_IN;
#pragma unroll
        for (int j = 0; j < NT / 32; j++) {
            int idx = tid + 256 * j;
            int ver = idx >= NT * 4;
            int loc = ver ? idx - NT * 4 : idx;
            int r = loc >> 2, seg = loc & 3;
            const __nv_bfloat16* src =
                (ver ? Wl : Wh) + ((size_t)e * N + nBase + r) * K_IN + i0 + seg * 8;
            CP_ASYNC16(st + 2 * AB + ver * BB + swz(r, seg), src);
        }
    };

    cp_stage(0, 0);
    CP_COMMIT();
    cp_stage(1, 1);
    CP_COMMIT();
    CP_WAIT1();
    __syncthreads();

    for (int c = 0; c < NC; c++) {
        const int s = c & 1;
        const uint32_t aB = sb + s * STG;
        const uint32_t bB = aB + 2 * AB;
#pragma unroll
        for (int kk = 0; kk < 2; kk++) {
            uint32_t bh[NP][4], bl[NP][4];
            const int mat = lid >> 3, ri = lid & 7;
#pragma unroll
            for (int p = 0; p < NP; p++) {
                int n = wn * WNC + p * 16 + ((mat >> 1) << 3) + ri;
                int seg = kk * 2 + (mat & 1);
                ldsm4(bh[p][0], bh[p][1], bh[p][2], bh[p][3], bB + swz(n, seg));
                ldsm4(bl[p][0], bl[p][1], bl[p][2], bl[p][3], bB + BB + swz(n, seg));
            }
#pragma unroll
            for (int mt = 0; mt < 4; mt++) {
                uint32_t ah[4], al[4];
                int r = wm * 64 + mt * 16 + ((mat & 1) << 3) + ri;
                int seg = kk * 2 + (mat >> 1);
                ldsm4(ah[0], ah[1], ah[2], ah[3], aB + swz(r, seg));
                ldsm4(al[0], al[1], al[2], al[3], aB + AB + swz(r, seg));
#pragma unroll
                for (int nt = 0; nt < NTT; nt++) {
                    const uint32_t* bph = &bh[nt >> 1][(nt & 1) * 2];
                    const uint32_t* bpl = &bl[nt >> 1][(nt & 1) * 2];
                    mma16816(acc[mt][nt], ah, bph);
                    mma16816(acc[mt][nt], al, bph);
                    mma16816(acc[mt][nt], ah, bpl);
                }
            }
        }
        __syncthreads();
        if (c + 2 < NC) cp_stage(s, c + 2);
        CP_COMMIT();
        CP_WAIT1();
        __syncthreads();
    }

    // ---- epilogue: blended bias + optional ELU ----
    float* biasS = (float*)smem;
    for (int i = tid; i < 8 * NT; i += 256)
        biasS[i] = Bias[(i / NT) * N + nBase + (i % NT)];
    __syncthreads();

#pragma unroll
    for (int mt = 0; mt < 4; mt++) {
#pragma unroll
        for (int hh = 0; hh < 2; hh++) {
            const int row = mBase + wm * 64 + mt * 16 + (lid >> 2) + hh * 8;
            float4 b0 = *(const float4*)(blend + (size_t)row * 8);
            float4 b1 = *(const float4*)(blend + (size_t)row * 8 + 4);
            float blv[8] = {b0.x, b0.y, b0.z, b0.w, b1.x, b1.y, b1.z, b1.w};
#pragma unroll
            for (int nt = 0; nt < NTT; nt++) {
                int col = wn * WNC + nt * 8 + (lid & 3) * 2;
                float v0 = acc[mt][nt][hh * 2 + 0];
                float v1 = acc[mt][nt][hh * 2 + 1];
                float bb0 = 0.f, bb1 = 0.f;
#pragma unroll
                for (int e = 0; e < 8; e++) {
                    bb0 += blv[e] * biasS[e * NT + col];
                    bb1 += blv[e] * biasS[e * NT + col + 1];
                }
                v0 += bb0;
                v1 += bb1;
                if (DO_ELU) {
                    v0 = (v0 > 0.f) ? v0 : expm1f(v0);
                    v1 = (v1 > 0.f) ? v1 : expm1f(v1);
                }
                *(float2*)(out + (size_t)row * N + nBase + col) = make_float2(v0, v1);
            }
        }
    }
}

// ---------------- host ----------------
extern "C" void kernel_launch(void* const* d_in, const int* in_sizes, int n_in,
                              void* d_out, int out_size) {
    const float* blend = (const float*)d_in[0];  // (4096, 8)
    const float* x     = (const float*)d_in[1];  // (4096, 512)
    const float* W0    = (const float*)d_in[2];  // (8, 1024, 512)
    const float* B0    = (const float*)d_in[3];
    const float* W1    = (const float*)d_in[4];  // (8, 1024, 1024)
    const float* B1    = (const float*)d_in[5];
    const float* W2    = (const float*)d_in[6];  // (8, 512, 1024)
    const float* B2    = (const float*)d_in[7];
    float* out = (float*)d_out;                  // (4096, 512)

    __nv_bfloat16 *ahi, *alo, *whi, *wlo;
    float* h;
    cudaGetSymbolAddress((void**)&ahi, g_Ahi);
    cudaGetSymbolAddress((void**)&alo, g_Alo);
    cudaGetSymbolAddress((void**)&whi, g_Whi);
    cudaGetSymbolAddress((void**)&wlo, g_Wlo);
    cudaGetSymbolAddress((void**)&h, g_h);

    // split weights into bf16 hi/lo (W0 @ 0, W1 @ 4M, W2 @ 12M elements)
    wsplit<<<512, 256>>>((const float4*)W0, (uint2*)whi, (uint2*)wlo, (8 * 1024 * 512) / 4);
    wsplit<<<512, 256>>>((const float4*)W1, (uint2*)(whi + 4194304), (uint2*)(wlo + 4194304),
                         (8 * 1024 * 1024) / 4);
    wsplit<<<512, 256>>>((const float4*)W2, (uint2*)(whi + 12582912), (uint2*)(wlo + 12582912),
                         (8 * 512 * 1024) / 4);

    constexpr int S256 = 2 * (2 * 128 * 64 + 2 * 256 * 64);  // 96KB
    constexpr int S128 = 2 * (2 * 128 * 64 + 2 * 128 * 64);  // 64KB
    cudaFuncSetAttribute(gemm_mma<512, 1024, 256, true>,
                         cudaFuncAttributeMaxDynamicSharedMemorySize, S256);
    cudaFuncSetAttribute(gemm_mma<1024, 1024, 256, true>,
                         cudaFuncAttributeMaxDynamicSharedMemorySize, S256);
    cudaFuncSetAttribute(gemm_mma<1024, 512, 128, false>,
                         cudaFuncAttributeMaxDynamicSharedMemorySize, S128);

    // layer 0
    prep<512><<<(4096 * 128 + 255) / 256, 256>>>(x, blend, ahi, alo);
    gemm_mma<512, 1024, 256, true><<<dim3(4, 32), 256, S256>>>(
        ahi, alo, whi, wlo, blend, B0, h);
    // layer 1
    prep<1024><<<(4096 * 256 + 255) / 256, 256>>>(h, blend, ahi, alo);
    gemm_mma<1024, 1024, 256, true><<<dim3(4, 32), 256, S256>>>(
        ahi, alo, whi + 4194304, wlo + 4194304, blend, B1, h);
    // layer 2
    prep<1024><<<(4096 * 256 + 255) / 256, 256>>>(h, blend, ahi, alo);
    gemm_mma<1024, 512, 128, false><<<dim3(4, 32), 256, S128>>>(
        ahi, alo, whi + 12582912, wlo + 12582912, blend, B2, out);
}

// round 4
// speedup vs baseline: 3.1085x; 1.1901x over previous
#include <cuda_runtime.h>
#include <cuda_bf16.h>
#include <cstdint>
#include <cstddef>

// ---------------- static device buffers (no runtime allocation) ----------------
// A planes, chunk-major pre-swizzled: [k/32][4096 rows][64B]
__device__ __align__(256) __nv_bfloat16 g_Ahi[4096 * 8192];
__device__ __align__(256) __nv_bfloat16 g_Alo[4096 * 8192];
// W planes, chunk-major pre-swizzled per layer: [k/32][N][64B]
// L0 @ 0 (4M el), L1 @ 4M (8M el), L2 @ 12M (4M el)
__device__ __align__(256) __nv_bfloat16 g_Whi[16 * 1024 * 1024];
__device__ __align__(256) __nv_bfloat16 g_Wlo[16 * 1024 * 1024];
__device__ __align__(256) float g_h[4096 * 1024];

// ---------------- helpers ----------------
__device__ __forceinline__ uint32_t smem_u32(const void* p) {
    uint32_t a;
    asm("{ .reg .u64 t; cvta.to.shared.u64 t, %1; cvt.u32.u64 %0, t; }" : "=r"(a) : "l"(p));
    return a;
}

#define MBAR_INIT(a, c) asm volatile("mbarrier.init.shared.b64 [%0], %1;" ::"r"(a), "r"(c) : "memory")
#define MBAR_EXPECT(a, n) \
    asm volatile("mbarrier.arrive.expect_tx.shared.b64 _, [%0], %1;" ::"r"(a), "r"(n) : "memory")
#define FENCE_ASYNC() asm volatile("fence.proxy.async.shared::cta;" ::: "memory")
#define CP_BULK(dst, src, bytes, mbar)                                                        \
    asm volatile(                                                                             \
        "cp.async.bulk.shared::cluster.global.mbarrier::complete_tx::bytes [%0], [%1], %2, [%3];" \
        ::"r"(dst), "l"(src), "r"(bytes), "r"(mbar) : "memory")
#define MBAR_WAIT(a, ph)                                                                           \
    do {                                                                                           \
        uint32_t _m = (a), _p = (ph), _d;                                                          \
        asm volatile(                                                                              \
            "{\n\t.reg .pred p;\n\t"                                                               \
            "mbarrier.try_wait.parity.acquire.cta.shared::cta.b64 p, [%1], %2;\n\t"                \
            "selp.b32 %0,1,0,p;\n\t}"                                                              \
            : "=r"(_d) : "r"(_m), "r"(_p) : "memory");                                             \
        if (!_d) {                                                                                 \
            asm volatile(                                                                          \
                "{\n\t.reg .pred P1;\n\t"                                                          \
                "WL%=:\n\t"                                                                        \
                "mbarrier.try_wait.parity.acquire.cta.shared::cta.b64 P1, [%0], %1, 0x989680;\n\t" \
                "@P1 bra.uni WD%=;\n\t"                                                            \
                "bra.uni WL%=;\n\t"                                                                \
                "WD%=:\n\t}" ::"r"(_m), "r"(_p) : "memory");                                       \
        }                                                                                          \
    } while (0)

__device__ __forceinline__ void ldsm4(uint32_t& r0, uint32_t& r1, uint32_t& r2, uint32_t& r3,
                                      uint32_t addr) {
    asm volatile("ldmatrix.sync.aligned.m8n8.x4.shared.b16 {%0,%1,%2,%3}, [%4];"
                 : "=r"(r0), "=r"(r1), "=r"(r2), "=r"(r3) : "r"(addr));
}

__device__ __forceinline__ void mma16816(float* c, const uint32_t* a, const uint32_t* b) {
    asm volatile(
        "mma.sync.aligned.m16n8k16.row.col.f32.bf16.bf16.f32 "
        "{%0,%1,%2,%3}, {%4,%5,%6,%7}, {%8,%9}, {%0,%1,%2,%3};"
        : "+f"(c[0]), "+f"(c[1]), "+f"(c[2]), "+f"(c[3])
        : "r"(a[0]), "r"(a[1]), "r"(a[2]), "r"(a[3]), "r"(b[0]), "r"(b[1]));
}

// fp32 -> bf16 hi/lo split, packed pairs (low 16 bits = first element)
__device__ __forceinline__ void split2(float a, float b, uint32_t& hi, uint32_t& lo) {
    __nv_bfloat16 ha = __float2bfloat16_rn(a), hb = __float2bfloat16_rn(b);
    float ra = a - __bfloat162float(ha);
    float rb = b - __bfloat162float(hb);
    __nv_bfloat16 la = __float2bfloat16_rn(ra), lb = __float2bfloat16_rn(rb);
    hi = (uint32_t)__bfloat16_as_ushort(ha) | ((uint32_t)__bfloat16_as_ushort(hb) << 16);
    lo = (uint32_t)__bfloat16_as_ushort(la) | ((uint32_t)__bfloat16_as_ushort(lb) << 16);
}

// in-tile swizzle: row*64 + ((seg ^ ((row>>1)&3))<<4)  (seg = 16B segment 0..3)
#define SWZ(row, seg) ((uint32_t)((row) * 64 + ((((seg) ^ (((row) >> 1) & 3))) << 4)))

// ---------------- weight split into chunk-major pre-swizzled layout ----------------
template <int N, int K_IN>
__global__ void wsplit(const float* __restrict__ W, __nv_bfloat16* __restrict__ hi,
                       __nv_bfloat16* __restrict__ lo) {
    constexpr int SEGS = K_IN / 8;
    int t = blockIdx.x * blockDim.x + threadIdx.x;
    if (t >= 8 * N * SEGS) return;
    int s8 = t % SEGS;
    int n = (t / SEGS) % N;
    int e = t / (N * SEGS);
    int i = s8 * 8;
    const float* src = W + ((size_t)e * N + n) * K_IN + i;
    float4 v0 = *(const float4*)src;
    float4 v1 = *(const float4*)(src + 4);
    uint4 H, L;
    split2(v0.x, v0.y, H.x, L.x);
    split2(v0.z, v0.w, H.y, L.y);
    split2(v1.x, v1.y, H.z, L.z);
    split2(v1.z, v1.w, H.w, L.w);
    int kg = e * K_IN + i;
    int chunk = kg >> 5, seg = (kg >> 3) & 3;
    size_t off = (size_t)chunk * (N * 64) + SWZ(n, seg);  // bytes
    *(uint4*)((char*)hi + off) = H;
    *(uint4*)((char*)lo + off) = L;
}

// ---------------- activation fold+split into chunk-major pre-swizzled layout ----------------
template <int K_IN>
__global__ void prep(const float* __restrict__ h, const float* __restrict__ blend,
                     __nv_bfloat16* __restrict__ Ahi, __nv_bfloat16* __restrict__ Alo) {
    constexpr int SEGS = K_IN / 8;
    int idx = blockIdx.x * blockDim.x + threadIdx.x;
    if (idx >= 4096 * SEGS) return;
    int b = idx / SEGS, s8 = idx % SEGS;
    int i = s8 * 8;
    const float* src = h + (size_t)b * K_IN + i;
    float4 v0 = *(const float4*)src;
    float4 v1 = *(const float4*)(src + 4);
    float4 w0 = *(const float4*)(blend + (size_t)b * 8);
    float4 w1 = *(const float4*)(blend + (size_t)b * 8 + 4);
    float wv[8] = {w0.x, w0.y, w0.z, w0.w, w1.x, w1.y, w1.z, w1.w};
#pragma unroll
    for (int e = 0; e < 8; e++) {
        float s = wv[e];
        uint4 H, L;
        split2(v0.x * s, v0.y * s, H.x, L.x);
        split2(v0.z * s, v0.w * s, H.y, L.y);
        split2(v1.x * s, v1.y * s, H.z, L.z);
        split2(v1.z * s, v1.w * s, H.w, L.w);
        int kg = e * K_IN + i;
        int chunk = kg >> 5, seg = (kg >> 3) & 3;
        size_t off = (size_t)chunk * (4096 * 64) + SWZ(b, seg);  // bytes
        *(uint4*)((char*)Ahi + off) = H;
        *(uint4*)((char*)Alo + off) = L;
    }
}

// ---------------- GEMM: C(4096,N) = A(4096,K) x W^T, 3-product bf16 split ----------------
// CTA tile MT x NT x 32. 8 warps; warp tile 32 x WNC. 3-stage cp.async.bulk pipeline.
template <int MT, int NT, int K, int N, bool DO_ELU>
__global__ __launch_bounds__(256, 2) void gemm_mma(
    const __nv_bfloat16* __restrict__ Ahi, const __nv_bfloat16* __restrict__ Alo,
    const __nv_bfloat16* __restrict__ Wh, const __nv_bfloat16* __restrict__ Wl,
    const float* __restrict__ blend, const float* __restrict__ Bias,
    float* __restrict__ out) {
    constexpr int NC = K / 32;
    constexpr int AB = MT * 64;   // bytes per A version tile
    constexpr int BB = NT * 64;   // bytes per B version tile
    constexpr int STG = 2 * AB + 2 * BB;
    constexpr int MB_OFF = 3 * STG;
    constexpr int MW = MT / 32;        // warps along M
    constexpr int WNC = NT * MW / 8;   // warp N extent
    constexpr int NP = WNC / 16;
    constexpr int NTT = WNC / 8;
    constexpr size_t CHA = 4096 * 64;  // A chunk stride (bytes)
    constexpr size_t CHB = (size_t)N * 64;

    extern __shared__ __align__(1024) char smem[];
    const uint32_t sb = smem_u32(smem);
    const int tid = threadIdx.x, wid = tid >> 5, lid = tid & 31;
    const int wm = wid % MW, wn = wid / MW;
    const int mBase = blockIdx.y * MT, nBase = blockIdx.x * NT;

    if (tid == 0) {
#pragma unroll
        for (int s = 0; s < 3; s++) MBAR_INIT(sb + MB_OFF + 8 * s, 1);
        FENCE_ASYNC();
    }
    __syncthreads();

    auto issue = [&](int s, int c) {
        const uint32_t st = sb + s * STG;
        const uint32_t mb = sb + MB_OFF + 8 * s;
        MBAR_EXPECT(mb, STG);
        CP_BULK(st,               (const char*)Ahi + (size_t)c * CHA + (size_t)mBase * 64, AB, mb);
        CP_BULK(st + AB,          (const char*)Alo + (size_t)c * CHA + (size_t)mBase * 64, AB, mb);
        CP_BULK(st + 2 * AB,      (const char*)Wh  + (size_t)c * CHB + (size_t)nBase * 64, BB, mb);
        CP_BULK(st + 2 * AB + BB, (const char*)Wl  + (size_t)c * CHB + (size_t)nBase * 64, BB, mb);
    };

    if (tid == 0) {
        issue(0, 0);
        issue(1, 1);
        issue(2, 2);
    }

    float acc[2][NTT][4];
#pragma unroll
    for (int a = 0; a < 2; a++)
#pragma unroll
        for (int b = 0; b < NTT; b++)
#pragma unroll
            for (int c = 0; c < 4; c++) acc[a][b][c] = 0.f;

    for (int c = 0; c < NC; c++) {
        const int s = c % 3;
        MBAR_WAIT(sb + MB_OFF + 8 * s, (c / 3) & 1);

        const uint32_t aB = sb + s * STG;
        const uint32_t bB = aB + 2 * AB;
        const int mat = lid >> 3, ri = lid & 7;
#pragma unroll
        for (int kk = 0; kk < 2; kk++) {
            uint32_t bh[NP][4], bl[NP][4];
#pragma unroll
            for (int p = 0; p < NP; p++) {
                int n = wn * WNC + p * 16 + ((mat >> 1) << 3) + ri;
                int seg = kk * 2 + (mat & 1);
                ldsm4(bh[p][0], bh[p][1], bh[p][2], bh[p][3], bB + SWZ(n, seg));
                ldsm4(bl[p][0], bl[p][1], bl[p][2], bl[p][3], bB + BB + SWZ(n, seg));
            }
#pragma unroll
            for (int mt = 0; mt < 2; mt++) {
                uint32_t ah[4], al[4];
                int r = wm * 32 + mt * 16 + ((mat & 1) << 3) + ri;
                int seg = kk * 2 + (mat >> 1);
                ldsm4(ah[0], ah[1], ah[2], ah[3], aB + SWZ(r, seg));
                ldsm4(al[0], al[1], al[2], al[3], aB + AB + SWZ(r, seg));
#pragma unroll
                for (int nt = 0; nt < NTT; nt++) {
                    const uint32_t* bph = &bh[nt >> 1][(nt & 1) * 2];
                    const uint32_t* bpl = &bl[nt >> 1][(nt & 1) * 2];
                    mma16816(acc[mt][nt], ah, bph);
                    mma16816(acc[mt][nt], al, bph);
                    mma16816(acc[mt][nt], ah, bpl);
                }
            }
        }
        __syncthreads();  // all warps done reading stage s
        if (tid == 0 && c + 3 < NC) issue(s, c + 3);
    }

    // ---- epilogue: blended bias + optional ELU ----
    float* biasS = (float*)smem;
    for (int i = tid; i < 8 * NT; i += 256)
        biasS[i] = Bias[(i / NT) * N + nBase + (i % NT)];
    __syncthreads();

#pragma unroll
    for (int mt = 0; mt < 2; mt++) {
#pragma unroll
        for (int hh = 0; hh < 2; hh++) {
            const int row = mBase + wm * 32 + mt * 16 + (lid >> 2) + hh * 8;
            float4 b0 = *(const float4*)(blend + (size_t)row * 8);
            float4 b1 = *(const float4*)(blend + (size_t)row * 8 + 4);
            float blv[8] = {b0.x, b0.y, b0.z, b0.w, b1.x, b1.y, b1.z, b1.w};
#pragma unroll
            for (int nt = 0; nt < NTT; nt++) {
                int col = wn * WNC + nt * 8 + (lid & 3) * 2;
                float v0 = acc[mt][nt][hh * 2 + 0];
                float v1 = acc[mt][nt][hh * 2 + 1];
                float bb0 = 0.f, bb1 = 0.f;
#pragma unroll
                for (int e = 0; e < 8; e++) {
                    bb0 += blv[e] * biasS[e * NT + col];
                    bb1 += blv[e] * biasS[e * NT + col + 1];
                }
                v0 += bb0;
                v1 += bb1;
                if (DO_ELU) {
                    v0 = (v0 > 0.f) ? v0 : expm1f(v0);
                    v1 = (v1 > 0.f) ? v1 : expm1f(v1);
                }
                *(float2*)(out + (size_t)row * N + nBase + col) = make_float2(v0, v1);
            }
        }
    }
}

// ---------------- host ----------------
extern "C" void kernel_launch(void* const* d_in, const int* in_sizes, int n_in,
                              void* d_out, int out_size) {
    const float* blend = (const float*)d_in[0];  // (4096, 8)
    const float* x     = (const float*)d_in[1];  // (4096, 512)
    const float* W0    = (const float*)d_in[2];  // (8, 1024, 512)
    const float* B0    = (const float*)d_in[3];
    const float* W1    = (const float*)d_in[4];  // (8, 1024, 1024)
    const float* B1    = (const float*)d_in[5];
    const float* W2    = (const float*)d_in[6];  // (8, 512, 1024)
    const float* B2    = (const float*)d_in[7];
    float* out = (float*)d_out;                  // (4096, 512)

    __nv_bfloat16 *ahi, *alo, *whi, *wlo;
    float* h;
    cudaGetSymbolAddress((void**)&ahi, g_Ahi);
    cudaGetSymbolAddress((void**)&alo, g_Alo);
    cudaGetSymbolAddress((void**)&whi, g_Whi);
    cudaGetSymbolAddress((void**)&wlo, g_Wlo);
    cudaGetSymbolAddress((void**)&h, g_h);

    // weight splits into chunk-major pre-swizzled layout
    wsplit<1024, 512><<<(8 * 1024 * 64 + 255) / 256, 256>>>(W0, whi, wlo);
    wsplit<1024, 1024><<<(8 * 1024 * 128 + 255) / 256, 256>>>(W1, whi + 4194304, wlo + 4194304);
    wsplit<512, 1024><<<(8 * 512 * 128 + 255) / 256, 256>>>(W2, whi + 12582912, wlo + 12582912);

    constexpr int S_L01 = 3 * (2 * 128 * 64 + 2 * 128 * 64) + 32;  // 96KB + bars
    constexpr int S_L2  = 3 * (2 * 64 * 64 + 2 * 128 * 64) + 32;   // 72KB + bars
    cudaFuncSetAttribute(gemm_mma<128, 128, 4096, 1024, true>,
                         cudaFuncAttributeMaxDynamicSharedMemorySize, S_L01);
    cudaFuncSetAttribute(gemm_mma<128, 128, 8192, 1024, true>,
                         cudaFuncAttributeMaxDynamicSharedMemorySize, S_L01);
    cudaFuncSetAttribute(gemm_mma<64, 128, 8192, 512, false>,
                         cudaFuncAttributeMaxDynamicSharedMemorySize, S_L2);

    // layer 0: (4096,512) -> (4096,1024), ELU
    prep<512><<<(4096 * 64 + 255) / 256, 256>>>(x, blend, ahi, alo);
    gemm_mma<128, 128, 4096, 1024, true><<<dim3(8, 32), 256, S_L01>>>(
        ahi, alo, whi, wlo, blend, B0, h);
    // layer 1: (4096,1024) -> (4096,1024), ELU
    prep<1024><<<(4096 * 128 + 255) / 256, 256>>>(h, blend, ahi, alo);
    gemm_mma<128, 128, 8192, 1024, true><<<dim3(8, 32), 256, S_L01>>>(
        ahi, alo, whi + 4194304, wlo + 4194304, blend, B1, h);
    // layer 2: (4096,1024) -> (4096,512), linear
    prep<1024><<<(4096 * 128 + 255) / 256, 256>>>(h, blend, ahi, alo);
    gemm_mma<64, 128, 8192, 512, false><<<dim3(4, 64), 256, S_L2>>>(
        ahi, alo, whi + 12582912, wlo + 12582912, blend, B2, out);
}

// round 5
// speedup vs baseline: 4.4962x; 1.4464x over previous
#include <cuda_runtime.h>
#include <cuda_fp16.h>
#include <cstdint>
#include <cstddef>

// ---------------- static device buffers (no runtime allocation) ----------------
// A plane (single fp16), chunk-major pre-swizzled: [k/32][4096 rows][64B]
__device__ __align__(256) __half g_Ah[4096 * 8192];
// W planes (fp16 hi/lo), chunk-major pre-swizzled per layer: [k/32][N][64B]
// L0 @ 0 (4M el), L1 @ 4M (8M el), L2 @ 12M (4M el)
__device__ __align__(256) __half g_Wh[16 * 1024 * 1024];
__device__ __align__(256) __half g_Wl[16 * 1024 * 1024];
__device__ __align__(256) float g_h[4096 * 1024];

// ---------------- helpers ----------------
__device__ __forceinline__ uint32_t smem_u32(const void* p) {
    uint32_t a;
    asm("{ .reg .u64 t; cvta.to.shared.u64 t, %1; cvt.u32.u64 %0, t; }" : "=r"(a) : "l"(p));
    return a;
}

#define MBAR_INIT(a, c) asm volatile("mbarrier.init.shared.b64 [%0], %1;" ::"r"(a), "r"(c) : "memory")
#define MBAR_EXPECT(a, n) \
    asm volatile("mbarrier.arrive.expect_tx.shared.b64 _, [%0], %1;" ::"r"(a), "r"(n) : "memory")
#define FENCE_ASYNC() asm volatile("fence.proxy.async.shared::cta;" ::: "memory")
#define CP_BULK(dst, src, bytes, mbar)                                                        \
    asm volatile(                                                                             \
        "cp.async.bulk.shared::cluster.global.mbarrier::complete_tx::bytes [%0], [%1], %2, [%3];" \
        ::"r"(dst), "l"(src), "r"(bytes), "r"(mbar) : "memory")
#define MBAR_WAIT(a, ph)                                                                           \
    do {                                                                                           \
        uint32_t _m = (a), _p = (ph), _d;                                                          \
        asm volatile(                                                                              \
            "{\n\t.reg .pred p;\n\t"                                                               \
            "mbarrier.try_wait.parity.acquire.cta.shared::cta.b64 p, [%1], %2;\n\t"                \
            "selp.b32 %0,1,0,p;\n\t}"                                                              \
            : "=r"(_d) : "r"(_m), "r"(_p) : "memory");                                             \
        if (!_d) {                                                                                 \
            asm volatile(                                                                          \
                "{\n\t.reg .pred P1;\n\t"                                                          \
                "WL%=:\n\t"                                                                        \
                "mbarrier.try_wait.parity.acquire.cta.shared::cta.b64 P1, [%0], %1, 0x989680;\n\t" \
                "@P1 bra.uni WD%=;\n\t"                                                            \
                "bra.uni WL%=;\n\t"                                                                \
                "WD%=:\n\t}" ::"r"(_m), "r"(_p) : "memory");                                       \
        }                                                                                          \
    } while (0)

__device__ __forceinline__ void ldsm4(uint32_t& r0, uint32_t& r1, uint32_t& r2, uint32_t& r3,
                                      uint32_t addr) {
    asm volatile("ldmatrix.sync.aligned.m8n8.x4.shared.b16 {%0,%1,%2,%3}, [%4];"
                 : "=r"(r0), "=r"(r1), "=r"(r2), "=r"(r3) : "r"(addr));
}

__device__ __forceinline__ void mma16816(float* c, const uint32_t* a, const uint32_t* b) {
    asm volatile(
        "mma.sync.aligned.m16n8k16.row.col.f32.f16.f16.f32 "
        "{%0,%1,%2,%3}, {%4,%5,%6,%7}, {%8,%9}, {%0,%1,%2,%3};"
        : "+f"(c[0]), "+f"(c[1]), "+f"(c[2]), "+f"(c[3])
        : "r"(a[0]), "r"(a[1]), "r"(a[2]), "r"(a[3]), "r"(b[0]), "r"(b[1]));
}

__device__ __forceinline__ uint32_t pkh2(float a, float b) {
    __half2 t = __floats2half2_rn(a, b);
    return *(uint32_t*)&t;
}

// fp16 hi/lo split of a pair
__device__ __forceinline__ void splitp(float a, float b, uint32_t& hi, uint32_t& lo) {
    __half ha = __float2half_rn(a), hb = __float2half_rn(b);
    float ra = a - __half2float(ha);
    float rb = b - __half2float(hb);
    __half la = __float2half_rn(ra), lb = __float2half_rn(rb);
    hi = (uint32_t)__half_as_ushort(ha) | ((uint32_t)__half_as_ushort(hb) << 16);
    lo = (uint32_t)__half_as_ushort(la) | ((uint32_t)__half_as_ushort(lb) << 16);
}

// in-tile swizzle: row*64 + ((seg ^ ((row>>1)&3))<<4)  (seg = 16B segment 0..3)
#define SWZ(row, seg) ((uint32_t)((row) * 64 + ((((seg) ^ (((row) >> 1) & 3))) << 4)))

// ---------------- weight split (fp16 hi/lo) into chunk-major pre-swizzled layout ----------------
template <int N, int K_IN>
__global__ void wsplit(const float* __restrict__ W, __half* __restrict__ hi,
                       __half* __restrict__ lo) {
    constexpr int SEGS = K_IN / 8;
    int t = blockIdx.x * blockDim.x + threadIdx.x;
    if (t >= 8 * N * SEGS) return;
    int s8 = t % SEGS;
    int n = (t / SEGS) % N;
    int e = t / (N * SEGS);
    int i = s8 * 8;
    const float* src = W + ((size_t)e * N + n) * K_IN + i;
    float4 v0 = *(const float4*)src;
    float4 v1 = *(const float4*)(src + 4);
    uint4 H, L;
    splitp(v0.x, v0.y, H.x, L.x);
    splitp(v0.z, v0.w, H.y, L.y);
    splitp(v1.x, v1.y, H.z, L.z);
    splitp(v1.z, v1.w, H.w, L.w);
    int kg = e * K_IN + i;
    int chunk = kg >> 5, seg = (kg >> 3) & 3;
    size_t off = (size_t)chunk * (N * 64) + SWZ(n, seg);  // bytes
    *(uint4*)((char*)hi + off) = H;
    *(uint4*)((char*)lo + off) = L;
}

// ---------------- activation fold (single fp16 plane): A[b, e*K_IN+i] = blend[b,e]*h[b,i] ----
template <int K_IN>
__global__ void prep(const float* __restrict__ h, const float* __restrict__ blend,
                     __half* __restrict__ Ah) {
    constexpr int SEGS = K_IN / 8;
    int idx = blockIdx.x * blockDim.x + threadIdx.x;
    if (idx >= 4096 * SEGS) return;
    int b = idx / SEGS, s8 = idx % SEGS;
    int i = s8 * 8;
    const float* src = h + (size_t)b * K_IN + i;
    float4 v0 = *(const float4*)src;
    float4 v1 = *(const float4*)(src + 4);
    float4 w0 = *(const float4*)(blend + (size_t)b * 8);
    float4 w1 = *(const float4*)(blend + (size_t)b * 8 + 4);
    float wv[8] = {w0.x, w0.y, w0.z, w0.w, w1.x, w1.y, w1.z, w1.w};
#pragma unroll
    for (int e = 0; e < 8; e++) {
        float s = wv[e];
        uint4 H;
        H.x = pkh2(v0.x * s, v0.y * s);
        H.y = pkh2(v0.z * s, v0.w * s);
        H.z = pkh2(v1.x * s, v1.y * s);
        H.w = pkh2(v1.z * s, v1.w * s);
        int kg = e * K_IN + i;
        int chunk = kg >> 5, seg = (kg >> 3) & 3;
        size_t off = (size_t)chunk * (4096 * 64) + SWZ(b, seg);  // bytes
        *(uint4*)((char*)Ah + off) = H;
    }
}

// ---------------- GEMM: C(4096,N) = A(4096,K) x W^T, 2-product fp16 (B split) -------------
// CTA tile MT x NT x 32. 8 warps; warp tile 32 x WNC. 4-stage cp.async.bulk pipeline.
template <int MT, int NT, int K, int N, bool DO_ELU>
__global__ __launch_bounds__(256, 2) void gemm_mma(
    const __half* __restrict__ Ah,
    const __half* __restrict__ Wh, const __half* __restrict__ Wl,
    const float* __restrict__ blend, const float* __restrict__ Bias,
    float* __restrict__ out) {
    constexpr int NC = K / 32;
    constexpr int NST = 4;
    constexpr int AB = MT * 64;   // bytes: A tile (single plane)
    constexpr int BB = NT * 64;   // bytes per B version tile
    constexpr int STG = AB + 2 * BB;
    constexpr int MB_OFF = NST * STG;
    constexpr int MW = MT / 32;        // warps along M
    constexpr int WNC = NT * MW / 8;   // warp N extent
    constexpr int NP = WNC / 16;
    constexpr int NTT = WNC / 8;
    constexpr size_t CHA = 4096 * 64;  // A chunk stride (bytes)
    constexpr size_t CHB = (size_t)N * 64;

    extern __shared__ __align__(1024) char smem[];
    const uint32_t sb = smem_u32(smem);
    const int tid = threadIdx.x, wid = tid >> 5, lid = tid & 31;
    const int wm = wid % MW, wn = wid / MW;
    const int mBase = blockIdx.y * MT, nBase = blockIdx.x * NT;

    if (tid == 0) {
#pragma unroll
        for (int s = 0; s < NST; s++) MBAR_INIT(sb + MB_OFF + 8 * s, 1);
        FENCE_ASYNC();
    }
    __syncthreads();

    auto issue = [&](int s, int c) {
        const uint32_t st = sb + s * STG;
        const uint32_t mb = sb + MB_OFF + 8 * s;
        MBAR_EXPECT(mb, STG);
        CP_BULK(st,           (const char*)Ah + (size_t)c * CHA + (size_t)mBase * 64, AB, mb);
        CP_BULK(st + AB,      (const char*)Wh + (size_t)c * CHB + (size_t)nBase * 64, BB, mb);
        CP_BULK(st + AB + BB, (const char*)Wl + (size_t)c * CHB + (size_t)nBase * 64, BB, mb);
    };

    if (tid == 0) {
#pragma unroll
        for (int s = 0; s < NST; s++) issue(s, s);
    }

    float acc[2][NTT][4];
#pragma unroll
    for (int a = 0; a < 2; a++)
#pragma unroll
        for (int b = 0; b < NTT; b++)
#pragma unroll
            for (int c = 0; c < 4; c++) acc[a][b][c] = 0.f;

    for (int c = 0; c < NC; c++) {
        const int s = c % NST;
        MBAR_WAIT(sb + MB_OFF + 8 * s, (c / NST) & 1);

        const uint32_t aB = sb + s * STG;
        const uint32_t bB = aB + AB;
        const int mat = lid >> 3, ri = lid & 7;
#pragma unroll
        for (int kk = 0; kk < 2; kk++) {
            uint32_t bh[NP][4], bl[NP][4];
#pragma unroll
            for (int p = 0; p < NP; p++) {
                int n = wn * WNC + p * 16 + ((mat >> 1) << 3) + ri;
                int seg = kk * 2 + (mat & 1);
                ldsm4(bh[p][0], bh[p][1], bh[p][2], bh[p][3], bB + SWZ(n, seg));
                ldsm4(bl[p][0], bl[p][1], bl[p][2], bl[p][3], bB + BB + SWZ(n, seg));
            }
#pragma unroll
            for (int mt = 0; mt < 2; mt++) {
                uint32_t ah[4];
                int r = wm * 32 + mt * 16 + ((mat & 1) << 3) + ri;
                int seg = kk * 2 + (mat >> 1);
                ldsm4(ah[0], ah[1], ah[2], ah[3], aB + SWZ(r, seg));
#pragma unroll
                for (int nt = 0; nt < NTT; nt++) {
                    const uint32_t* bph = &bh[nt >> 1][(nt & 1) * 2];
                    const uint32_t* bpl = &bl[nt >> 1][(nt & 1) * 2];
                    mma16816(acc[mt][nt], ah, bph);
                    mma16816(acc[mt][nt], ah, bpl);
                }
            }
        }
        __syncthreads();  // all warps done reading stage s
        if (tid == 0 && c + NST < NC) issue(s, c + NST);
    }

    // ---- epilogue: blended bias + optional ELU ----
    float* biasS = (float*)smem;
    for (int i = tid; i < 8 * NT; i += 256)
        biasS[i] = Bias[(i / NT) * N + nBase + (i % NT)];
    __syncthreads();

#pragma unroll
    for (int mt = 0; mt < 2; mt++) {
#pragma unroll
        for (int hh = 0; hh < 2; hh++) {
            const int row = mBase + wm * 32 + mt * 16 + (lid >> 2) + hh * 8;
            float4 b0 = *(const float4*)(blend + (size_t)row * 8);
            float4 b1 = *(const float4*)(blend + (size_t)row * 8 + 4);
            float blv[8] = {b0.x, b0.y, b0.z, b0.w, b1.x, b1.y, b1.z, b1.w};
#pragma unroll
            for (int nt = 0; nt < NTT; nt++) {
                int col = wn * WNC + nt * 8 + (lid & 3) * 2;
                float v0 = acc[mt][nt][hh * 2 + 0];
                float v1 = acc[mt][nt][hh * 2 + 1];
                float bb0 = 0.f, bb1 = 0.f;
#pragma unroll
                for (int e = 0; e < 8; e++) {
                    bb0 += blv[e] * biasS[e * NT + col];
                    bb1 += blv[e] * biasS[e * NT + col + 1];
                }
                v0 += bb0;
                v1 += bb1;
                if (DO_ELU) {
                    v0 = (v0 > 0.f) ? v0 : expm1f(v0);
                    v1 = (v1 > 0.f) ? v1 : expm1f(v1);
                }
                *(float2*)(out + (size_t)row * N + nBase + col) = make_float2(v0, v1);
            }
        }
    }
}

// ---------------- host ----------------
extern "C" void kernel_launch(void* const* d_in, const int* in_sizes, int n_in,
                              void* d_out, int out_size) {
    const float* blend = (const float*)d_in[0];  // (4096, 8)
    const float* x     = (const float*)d_in[1];  // (4096, 512)
    const float* W0    = (const float*)d_in[2];  // (8, 1024, 512)
    const float* B0    = (const float*)d_in[3];
    const float* W1    = (const float*)d_in[4];  // (8, 1024, 1024)
    const float* B1    = (const float*)d_in[5];
    const float* W2    = (const float*)d_in[6];  // (8, 512, 1024)
    const float* B2    = (const float*)d_in[7];
    float* out = (float*)d_out;                  // (4096, 512)

    __half *ah, *wh, *wl;
    float* h;
    cudaGetSymbolAddress((void**)&ah, g_Ah);
    cudaGetSymbolAddress((void**)&wh, g_Wh);
    cudaGetSymbolAddress((void**)&wl, g_Wl);
    cudaGetSymbolAddress((void**)&h, g_h);

    // weight splits into chunk-major pre-swizzled layout
    wsplit<1024, 512><<<(8 * 1024 * 64 + 255) / 256, 256>>>(W0, wh, wl);
    wsplit<1024, 1024><<<(8 * 1024 * 128 + 255) / 256, 256>>>(W1, wh + 4194304, wl + 4194304);
    wsplit<512, 1024><<<(8 * 512 * 128 + 255) / 256, 256>>>(W2, wh + 12582912, wl + 12582912);

    constexpr int S_L01 = 4 * (128 * 64 + 2 * 128 * 64) + 64;  // 96KB + bars
    constexpr int S_L2  = 4 * (64 * 64 + 2 * 128 * 64) + 64;   // 80KB + bars
    cudaFuncSetAttribute(gemm_mma<128, 128, 4096, 1024, true>,
                         cudaFuncAttributeMaxDynamicSharedMemorySize, S_L01);
    cudaFuncSetAttribute(gemm_mma<128, 128, 8192, 1024, true>,
                         cudaFuncAttributeMaxDynamicSharedMemorySize, S_L01);
    cudaFuncSetAttribute(gemm_mma<64, 128, 8192, 512, false>,
                         cudaFuncAttributeMaxDynamicSharedMemorySize, S_L2);

    // layer 0: (4096,512) -> (4096,1024), ELU
    prep<512><<<(4096 * 64 + 255) / 256, 256>>>(x, blend, ah);
    gemm_mma<128, 128, 4096, 1024, true><<<dim3(8, 32), 256, S_L01>>>(
        ah, wh, wl, blend, B0, h);
    // layer 1: (4096,1024) -> (4096,1024), ELU
    prep<1024><<<(4096 * 128 + 255) / 256, 256>>>(h, blend, ah);
    gemm_mma<128, 128, 8192, 1024, true><<<dim3(8, 32), 256, S_L01>>>(
        ah, wh + 4194304, wl + 4194304, blend, B1, h);
    // layer 2: (4096,1024) -> (4096,512), linear
    prep<1024><<<(4096 * 128 + 255) / 256, 256>>>(h, blend, ah);
    gemm_mma<64, 128, 8192, 512, false><<<dim3(4, 64), 256, S_L2>>>(
        ah, wh + 12582912, wl + 12582912, blend, B2, out);
}